// round 2
// baseline (speedup 1.0000x reference)
#include <cuda_runtime.h>
#include <math.h>

#define NJ 23
#define NP 16

// Packed skinning matrices: [j][pp][i*4+k][par] where pp = pose pair index,
// par selects pose (2*pp + par). Stored as interleaved f32 pairs for f32x2 FMA.
__device__ float g_A2[NJ * 8 * 24];

__constant__ int c_par[NJ]  = {-1,0,1,1,3,4,5,4,7,4,9,1,11,12,13,12,15,12,17,0,19,0,21};
__constant__ int c_slot[NJ] = {0,-1,-1,1,2,3,-1,4,-1,5,-1,6,7,8,-1,9,-1,10,-1,-1,-1,-1,-1};
__constant__ float c_scale[11] = {
    0.7853981633974483f, 1.5707963267948966f, 1.5707963267948966f,
    0.7853981633974483f, 0.7853981633974483f, 0.7853981633974483f,
    1.5707963267948966f, 1.5707963267948966f, 0.7853981633974483f,
    0.7853981633974483f, 0.7853981633974483f};
__constant__ int c_lvl[NJ]  = {0,1,2,2,3,4,5,4,5,4,5,2,3,4,5,4,5,4,5,1,2,1,2};

struct Ptrs11 { const float* p[11]; };

// ---------------------------------------------------------------------------
// Stage 1: per-(pose, joint) kinematics. 368 active threads, tree resolved by
// level with __syncthreads between levels. Writes posed joints (+shift) to the
// tail of d_out and packed per-joint skinning matrices A (shift folded into
// translation) to g_A2.
// ---------------------------------------------------------------------------
__global__ void lbs_pose_kernel(const float* __restrict__ joints,
                                const float* __restrict__ disp,
                                const float* __restrict__ rdis,
                                Ptrs11 prm,
                                float* __restrict__ out, int V)
{
    __shared__ float sT[NP][NJ][12];
    __shared__ float sG[NP][NJ][12];
    int t = threadIdx.x;
    int p = t / NJ, jj = t - p * NJ;
    bool act = (t < NP * NJ);

    if (act) {
        int s = c_slot[jj];
        float rx = 0.f, ry = 0.f, rz = 0.f;
        if (s >= 0) {
            const float* q = prm.p[s] + p * 3;
            float sc = c_scale[s];
            rx = sc * tanhf(q[0]); ry = sc * tanhf(q[1]); rz = sc * tanhf(q[2]);
        }
        // Rodrigues (matches reference: angle = sqrt(|r|^2 + 1e-16))
        float th = sqrtf(rx * rx + ry * ry + rz * rz + 1e-16f);
        float inv = 1.f / th;
        float ax = rx * inv, ay = ry * inv, az = rz * inv;
        float sn = sinf(th), cs = cosf(th), oc = 1.f - cs;
        float* T = sT[p][jj];
        T[0] = cs + oc * ax * ax;      T[1] = oc * ax * ay - sn * az; T[2]  = oc * ax * az + sn * ay;
        T[4] = oc * ax * ay + sn * az; T[5] = cs + oc * ay * ay;      T[6]  = oc * ay * az - sn * ax;
        T[8] = oc * ax * az - sn * ay; T[9] = oc * ay * az + sn * ax; T[10] = cs + oc * az * az;
        float relx = joints[jj * 3 + 0], rely = joints[jj * 3 + 1], relz = joints[jj * 3 + 2];
        if (jj > 0) {
            int pa = c_par[jj];
            relx -= joints[pa * 3 + 0];
            rely -= joints[pa * 3 + 1];
            relz -= joints[pa * 3 + 2];
        }
        T[3] = relx; T[7] = rely; T[11] = relz;
        if (jj == 0) {
            float* G = sG[p][0];
            #pragma unroll
            for (int i = 0; i < 12; i++) G[i] = T[i];
        }
    }
    __syncthreads();

    #pragma unroll
    for (int l = 1; l <= 5; l++) {
        if (act && c_lvl[jj] == l) {
            int pa = c_par[jj];
            const float* Gp = sG[p][pa];
            const float* Tl = sT[p][jj];
            float* Gc = sG[p][jj];
            #pragma unroll
            for (int i = 0; i < 3; i++) {
                float a0 = Gp[i * 4 + 0], a1 = Gp[i * 4 + 1], a2 = Gp[i * 4 + 2];
                Gc[i * 4 + 0] = a0 * Tl[0] + a1 * Tl[4] + a2 * Tl[8];
                Gc[i * 4 + 1] = a0 * Tl[1] + a1 * Tl[5] + a2 * Tl[9];
                Gc[i * 4 + 2] = a0 * Tl[2] + a1 * Tl[6] + a2 * Tl[10];
                Gc[i * 4 + 3] = a0 * Tl[3] + a1 * Tl[7] + a2 * Tl[11] + Gp[i * 4 + 3];
            }
        }
        __syncthreads();
    }

    if (act) {
        float sh0 = rdis[p * 3 + 0] + 3.f * tanhf(disp[p * 3 + 0]);
        float sh1 = rdis[p * 3 + 1] + 3.f * tanhf(disp[p * 3 + 1]);
        float sh2 = rdis[p * 3 + 2] + 3.f * tanhf(disp[p * 3 + 2]);
        const float* G = sG[p][jj];

        // posed joints + shift -> output tail
        size_t jbase = (size_t)NP * V * 3 + ((size_t)p * NJ + jj) * 3;
        out[jbase + 0] = G[3]  + sh0;
        out[jbase + 1] = G[7]  + sh1;
        out[jbase + 2] = G[11] + sh2;

        // A[p,j] = [G_R | G_t - G_R @ j_rest + shift], packed as pose pairs
        float jx = joints[jj * 3 + 0], jy = joints[jj * 3 + 1], jz = joints[jj * 3 + 2];
        int pp = p >> 1, par = p & 1;
        float* dst = g_A2 + (size_t)((jj * 8 + pp) * 12) * 2 + par;
        float sh[3] = {sh0, sh1, sh2};
        #pragma unroll
        for (int i = 0; i < 3; i++) {
            float tr = G[i * 4 + 3] - (G[i * 4 + 0] * jx + G[i * 4 + 1] * jy + G[i * 4 + 2] * jz) + sh[i];
            dst[(i * 4 + 0) * 2] = G[i * 4 + 0];
            dst[(i * 4 + 1) * 2] = G[i * 4 + 1];
            dst[(i * 4 + 2) * 2] = G[i * 4 + 2];
            dst[(i * 4 + 3) * 2] = tr;
        }
    }
}

// ---------------------------------------------------------------------------
// f32x2 packed-FMA helpers (sm_100+, ptxas never emits these from C++)
// ---------------------------------------------------------------------------
__device__ __forceinline__ void fma2(unsigned long long& d, unsigned long long a,
                                     unsigned long long b) {
    asm("fma.rn.f32x2 %0, %1, %2, %0;" : "+l"(d) : "l"(a), "l"(b));
}
__device__ __forceinline__ unsigned long long pack2(float lo, float hi) {
    unsigned long long r;
    asm("mov.b64 %0, {%1, %2};" : "=l"(r) : "f"(lo), "f"(hi));
    return r;
}
__device__ __forceinline__ void unpack2(unsigned long long v, float& lo, float& hi) {
    asm("mov.b64 {%0, %1}, %2;" : "=f"(lo), "=f"(hi) : "l"(v));
}

// ---------------------------------------------------------------------------
// Stage 2: one thread per vertex. Computes all 16 poses (as 8 f32x2 pose
// pairs) for its vertex. A matrices broadcast from shared memory (LDS.128,
// uniform address). 2208 FFMA2 per thread.
// ---------------------------------------------------------------------------
__global__ void __launch_bounds__(256)
lbs_vert_kernel(const float* __restrict__ verts,
                const float* __restrict__ weights,
                float* __restrict__ out, int V)
{
    __shared__ __align__(16) float sA[NJ * 8 * 24];
    #pragma unroll 1
    for (int i = threadIdx.x; i < NJ * 8 * 24; i += 256) sA[i] = g_A2[i];
    __syncthreads();

    int v = blockIdx.x * 256 + threadIdx.x;
    if (v >= V) return;

    float x = __ldg(verts + 3 * v + 0);
    float y = __ldg(verts + 3 * v + 1);
    float z = __ldg(verts + 3 * v + 2);
    float w[NJ];
    const float* wr = weights + (size_t)v * NJ;
    #pragma unroll
    for (int j = 0; j < NJ; j++) w[j] = __ldg(wr + j);

    unsigned long long acc[8][3];
    #pragma unroll
    for (int pp = 0; pp < 8; pp++)
        #pragma unroll
        for (int i = 0; i < 3; i++) acc[pp][i] = 0ull;

    #pragma unroll 1
    for (int j = 0; j < NJ; j++) {
        float wj = w[j];
        unsigned long long s0 = pack2(wj * x, wj * x);
        unsigned long long s1 = pack2(wj * y, wj * y);
        unsigned long long s2 = pack2(wj * z, wj * z);
        unsigned long long s3 = pack2(wj, wj);
        const ulonglong2* r = (const ulonglong2*)(sA + j * 8 * 24);
        #pragma unroll
        for (int pp = 0; pp < 8; pp++) {
            ulonglong2 q0 = r[pp * 6 + 0], q1 = r[pp * 6 + 1], q2 = r[pp * 6 + 2];
            ulonglong2 q3 = r[pp * 6 + 3], q4 = r[pp * 6 + 4], q5 = r[pp * 6 + 5];
            fma2(acc[pp][0], q0.x, s0); fma2(acc[pp][0], q0.y, s1);
            fma2(acc[pp][0], q1.x, s2); fma2(acc[pp][0], q1.y, s3);
            fma2(acc[pp][1], q2.x, s0); fma2(acc[pp][1], q2.y, s1);
            fma2(acc[pp][1], q3.x, s2); fma2(acc[pp][1], q3.y, s3);
            fma2(acc[pp][2], q4.x, s0); fma2(acc[pp][2], q4.y, s1);
            fma2(acc[pp][2], q5.x, s2); fma2(acc[pp][2], q5.y, s3);
        }
    }

    size_t vb = (size_t)v * 3;
    size_t slab = (size_t)V * 3;
    #pragma unroll
    for (int pp = 0; pp < 8; pp++) {
        size_t b0 = (size_t)(2 * pp) * slab + vb;
        size_t b1 = b0 + slab;
        #pragma unroll
        for (int i = 0; i < 3; i++) {
            float lo, hi;
            unpack2(acc[pp][i], lo, hi);
            out[b0 + i] = lo;
            out[b1 + i] = hi;
        }
    }
}

// ---------------------------------------------------------------------------
// Launch. Input order (metadata): vertices, joints, weights, displacement,
// random_dis, joint_0, joint_3, joint_4, joint_5, joint_7, joint_9, joint_11,
// joint_12, joint_13, joint_15, joint_17.
// Output: [16*V*3 v_posed floats][16*23*3 posed_joints floats].
// ---------------------------------------------------------------------------
extern "C" void kernel_launch(void* const* d_in, const int* in_sizes, int n_in,
                              void* d_out, int out_size)
{
    const float* verts   = (const float*)d_in[0];
    const float* joints  = (const float*)d_in[1];
    const float* weights = (const float*)d_in[2];
    const float* disp    = (const float*)d_in[3];
    const float* rdis    = (const float*)d_in[4];
    Ptrs11 prm;
    for (int i = 0; i < 11; i++) prm.p[i] = (const float*)d_in[5 + i];
    int V = in_sizes[0] / 3;
    float* out = (float*)d_out;

    lbs_pose_kernel<<<1, 384>>>(joints, disp, rdis, prm, out, V);
    int nb = (V + 255) / 256;
    lbs_vert_kernel<<<nb, 256>>>(verts, weights, out, V);
}

// round 4
// speedup vs baseline: 1.0954x; 1.0954x over previous
#include <cuda_runtime.h>
#include <math.h>

#define NJ 23
#define NP 16
#define TPB 128   // threads per block (vert kernel)
#define VPB 256   // vertices per block (2 per thread)

// Packed skinning matrices: [j][pp][i*4+k][par] where pp = pose pair index,
// par selects pose (2*pp + par). Interleaved f32 pairs for f32x2 FMA.
__device__ float g_A2[NJ * 8 * 24];

__constant__ int c_par[NJ]  = {-1,0,1,1,3,4,5,4,7,4,9,1,11,12,13,12,15,12,17,0,19,0,21};
__constant__ int c_slot[NJ] = {0,-1,-1,1,2,3,-1,4,-1,5,-1,6,7,8,-1,9,-1,10,-1,-1,-1,-1,-1};
__constant__ float c_scale[11] = {
    0.7853981633974483f, 1.5707963267948966f, 1.5707963267948966f,
    0.7853981633974483f, 0.7853981633974483f, 0.7853981633974483f,
    1.5707963267948966f, 1.5707963267948966f, 0.7853981633974483f,
    0.7853981633974483f, 0.7853981633974483f};
__constant__ int c_lvl[NJ]  = {0,1,2,2,3,4,5,4,5,4,5,2,3,4,5,4,5,4,5,1,2,1,2};

struct Ptrs11 { const float* p[11]; };

// ---------------------------------------------------------------------------
// Stage 1: per-(pose, joint) kinematics. Tree resolved level-by-level.
// Writes posed joints (+shift) to output tail and packed A matrices to g_A2.
// ---------------------------------------------------------------------------
__global__ void lbs_pose_kernel(const float* __restrict__ joints,
                                const float* __restrict__ disp,
                                const float* __restrict__ rdis,
                                Ptrs11 prm,
                                float* __restrict__ out, int V)
{
    __shared__ float sT[NP][NJ][12];
    __shared__ float sG[NP][NJ][12];
    int t = threadIdx.x;
    int p = t / NJ, jj = t - p * NJ;
    bool act = (t < NP * NJ);

    if (act) {
        int s = c_slot[jj];
        float rx = 0.f, ry = 0.f, rz = 0.f;
        if (s >= 0) {
            const float* q = prm.p[s] + p * 3;
            float sc = c_scale[s];
            rx = sc * tanhf(q[0]); ry = sc * tanhf(q[1]); rz = sc * tanhf(q[2]);
        }
        float th = sqrtf(rx * rx + ry * ry + rz * rz + 1e-16f);
        float inv = 1.f / th;
        float ax = rx * inv, ay = ry * inv, az = rz * inv;
        float sn = sinf(th), cs = cosf(th), oc = 1.f - cs;
        float* T = sT[p][jj];
        T[0] = cs + oc * ax * ax;      T[1] = oc * ax * ay - sn * az; T[2]  = oc * ax * az + sn * ay;
        T[4] = oc * ax * ay + sn * az; T[5] = cs + oc * ay * ay;      T[6]  = oc * ay * az - sn * ax;
        T[8] = oc * ax * az - sn * ay; T[9] = oc * ay * az + sn * ax; T[10] = cs + oc * az * az;
        float relx = joints[jj * 3 + 0], rely = joints[jj * 3 + 1], relz = joints[jj * 3 + 2];
        if (jj > 0) {
            int pa = c_par[jj];
            relx -= joints[pa * 3 + 0];
            rely -= joints[pa * 3 + 1];
            relz -= joints[pa * 3 + 2];
        }
        T[3] = relx; T[7] = rely; T[11] = relz;
        if (jj == 0) {
            float* G = sG[p][0];
            #pragma unroll
            for (int i = 0; i < 12; i++) G[i] = T[i];
        }
    }
    __syncthreads();

    #pragma unroll
    for (int l = 1; l <= 5; l++) {
        if (act && c_lvl[jj] == l) {
            int pa = c_par[jj];
            const float* Gp = sG[p][pa];
            const float* Tl = sT[p][jj];
            float* Gc = sG[p][jj];
            #pragma unroll
            for (int i = 0; i < 3; i++) {
                float a0 = Gp[i * 4 + 0], a1 = Gp[i * 4 + 1], a2 = Gp[i * 4 + 2];
                Gc[i * 4 + 0] = a0 * Tl[0] + a1 * Tl[4] + a2 * Tl[8];
                Gc[i * 4 + 1] = a0 * Tl[1] + a1 * Tl[5] + a2 * Tl[9];
                Gc[i * 4 + 2] = a0 * Tl[2] + a1 * Tl[6] + a2 * Tl[10];
                Gc[i * 4 + 3] = a0 * Tl[3] + a1 * Tl[7] + a2 * Tl[11] + Gp[i * 4 + 3];
            }
        }
        __syncthreads();
    }

    if (act) {
        float sh0 = rdis[p * 3 + 0] + 3.f * tanhf(disp[p * 3 + 0]);
        float sh1 = rdis[p * 3 + 1] + 3.f * tanhf(disp[p * 3 + 1]);
        float sh2 = rdis[p * 3 + 2] + 3.f * tanhf(disp[p * 3 + 2]);
        const float* G = sG[p][jj];

        size_t jbase = (size_t)NP * V * 3 + ((size_t)p * NJ + jj) * 3;
        out[jbase + 0] = G[3]  + sh0;
        out[jbase + 1] = G[7]  + sh1;
        out[jbase + 2] = G[11] + sh2;

        float jx = joints[jj * 3 + 0], jy = joints[jj * 3 + 1], jz = joints[jj * 3 + 2];
        int pp = p >> 1, par = p & 1;
        float* dst = g_A2 + (size_t)((jj * 8 + pp) * 12) * 2 + par;
        float sh[3] = {sh0, sh1, sh2};
        #pragma unroll
        for (int i = 0; i < 3; i++) {
            float tr = G[i * 4 + 3] - (G[i * 4 + 0] * jx + G[i * 4 + 1] * jy + G[i * 4 + 2] * jz) + sh[i];
            dst[(i * 4 + 0) * 2] = G[i * 4 + 0];
            dst[(i * 4 + 1) * 2] = G[i * 4 + 1];
            dst[(i * 4 + 2) * 2] = G[i * 4 + 2];
            dst[(i * 4 + 3) * 2] = tr;
        }
    }
}

// ---------------------------------------------------------------------------
// f32x2 packed-FMA helpers
// ---------------------------------------------------------------------------
__device__ __forceinline__ void fma2(unsigned long long& d, unsigned long long a,
                                     unsigned long long b) {
    asm("fma.rn.f32x2 %0, %1, %2, %0;" : "+l"(d) : "l"(a), "l"(b));
}
__device__ __forceinline__ unsigned long long pack2(float lo, float hi) {
    unsigned long long r;
    asm("mov.b64 %0, {%1, %2};" : "=l"(r) : "f"(lo), "f"(hi));
    return r;
}
__device__ __forceinline__ void unpack2(unsigned long long v, float& lo, float& hi) {
    asm("mov.b64 {%0, %1}, %2;" : "=f"(lo), "=f"(hi) : "l"(v));
}

// ---------------------------------------------------------------------------
// Stage 2: TWO vertices per thread — halves LDS traffic per vertex so the
// fma pipe (not L1) binds. Weights staged in smem (contiguous block slab,
// stride-23 reads are bank-conflict-free: 23 coprime to 32).
// Per warp: 4416*2 FFMA2 for 64 vertices, 1104 LDS.128 for A (amortized).
// ---------------------------------------------------------------------------
__global__ void __launch_bounds__(TPB)
lbs_vert_kernel(const float* __restrict__ verts,
                const float* __restrict__ weights,
                float* __restrict__ out, int V)
{
    __shared__ __align__(16) float sA[NJ * 8 * 24];   // 17664 B
    __shared__ __align__(16) float sW[VPB * NJ];      // 23552 B
    int t = threadIdx.x;
    int base = blockIdx.x * VPB;

    // stage A (float4)
    {
        const float4* g4 = (const float4*)g_A2;
        float4* s4 = (float4*)sA;
        #pragma unroll 1
        for (int i = t; i < NJ * 8 * 24 / 4; i += TPB) s4[i] = g4[i];
    }
    // stage weights slab (contiguous [VPB, NJ] region)
    {
        int rem = V - base;
        int nval = (rem >= VPB ? VPB : rem) * NJ;
        const float* slab = weights + (size_t)base * NJ;
        if (nval == VPB * NJ) {
            const float4* g4 = (const float4*)slab;
            float4* s4 = (float4*)sW;
            #pragma unroll 1
            for (int i = t; i < VPB * NJ / 4; i += TPB) s4[i] = g4[i];
        } else {
            #pragma unroll 1
            for (int i = t; i < nval; i += TPB) sW[i] = slab[i];
        }
    }
    __syncthreads();

    int v0 = base + t;
    int v1 = v0 + TPB;
    int vc0 = v0 < V ? v0 : V - 1;
    int vc1 = v1 < V ? v1 : V - 1;
    float x0 = verts[3 * vc0 + 0], y0 = verts[3 * vc0 + 1], z0 = verts[3 * vc0 + 2];
    float x1 = verts[3 * vc1 + 0], y1 = verts[3 * vc1 + 1], z1 = verts[3 * vc1 + 2];

    unsigned long long acc0[8][3], acc1[8][3];
    #pragma unroll
    for (int pp = 0; pp < 8; pp++)
        #pragma unroll
        for (int i = 0; i < 3; i++) { acc0[pp][i] = 0ull; acc1[pp][i] = 0ull; }

    #pragma unroll 1
    for (int j = 0; j < NJ; j++) {
        float w0 = sW[t * NJ + j];
        float w1 = sW[(t + TPB) * NJ + j];
        unsigned long long a0 = pack2(w0 * x0, w0 * x0);
        unsigned long long a1 = pack2(w0 * y0, w0 * y0);
        unsigned long long a2 = pack2(w0 * z0, w0 * z0);
        unsigned long long a3 = pack2(w0, w0);
        unsigned long long b0 = pack2(w1 * x1, w1 * x1);
        unsigned long long b1 = pack2(w1 * y1, w1 * y1);
        unsigned long long b2 = pack2(w1 * z1, w1 * z1);
        unsigned long long b3 = pack2(w1, w1);
        const ulonglong2* r = (const ulonglong2*)(sA + j * 8 * 24);
        #pragma unroll
        for (int pp = 0; pp < 8; pp++) {
            ulonglong2 q0 = r[pp * 6 + 0], q1 = r[pp * 6 + 1], q2 = r[pp * 6 + 2];
            ulonglong2 q3 = r[pp * 6 + 3], q4 = r[pp * 6 + 4], q5 = r[pp * 6 + 5];
            fma2(acc0[pp][0], q0.x, a0); fma2(acc0[pp][0], q0.y, a1);
            fma2(acc0[pp][0], q1.x, a2); fma2(acc0[pp][0], q1.y, a3);
            fma2(acc0[pp][1], q2.x, a0); fma2(acc0[pp][1], q2.y, a1);
            fma2(acc0[pp][1], q3.x, a2); fma2(acc0[pp][1], q3.y, a3);
            fma2(acc0[pp][2], q4.x, a0); fma2(acc0[pp][2], q4.y, a1);
            fma2(acc0[pp][2], q5.x, a2); fma2(acc0[pp][2], q5.y, a3);
            fma2(acc1[pp][0], q0.x, b0); fma2(acc1[pp][0], q0.y, b1);
            fma2(acc1[pp][0], q1.x, b2); fma2(acc1[pp][0], q1.y, b3);
            fma2(acc1[pp][1], q2.x, b0); fma2(acc1[pp][1], q2.y, b1);
            fma2(acc1[pp][1], q3.x, b2); fma2(acc1[pp][1], q3.y, b3);
            fma2(acc1[pp][2], q4.x, b0); fma2(acc1[pp][2], q4.y, b1);
            fma2(acc1[pp][2], q5.x, b2); fma2(acc1[pp][2], q5.y, b3);
        }
    }

    size_t slab = (size_t)V * 3;
    if (v0 < V) {
        size_t vb = (size_t)v0 * 3;
        #pragma unroll
        for (int pp = 0; pp < 8; pp++) {
            size_t c0 = (size_t)(2 * pp) * slab + vb;
            size_t c1 = c0 + slab;
            #pragma unroll
            for (int i = 0; i < 3; i++) {
                float lo, hi;
                unpack2(acc0[pp][i], lo, hi);
                out[c0 + i] = lo;
                out[c1 + i] = hi;
            }
        }
    }
    if (v1 < V) {
        size_t vb = (size_t)v1 * 3;
        #pragma unroll
        for (int pp = 0; pp < 8; pp++) {
            size_t c0 = (size_t)(2 * pp) * slab + vb;
            size_t c1 = c0 + slab;
            #pragma unroll
            for (int i = 0; i < 3; i++) {
                float lo, hi;
                unpack2(acc1[pp][i], lo, hi);
                out[c0 + i] = lo;
                out[c1 + i] = hi;
            }
        }
    }
}

// ---------------------------------------------------------------------------
// Launch.
// ---------------------------------------------------------------------------
extern "C" void kernel_launch(void* const* d_in, const int* in_sizes, int n_in,
                              void* d_out, int out_size)
{
    const float* verts   = (const float*)d_in[0];
    const float* joints  = (const float*)d_in[1];
    const float* weights = (const float*)d_in[2];
    const float* disp    = (const float*)d_in[3];
    const float* rdis    = (const float*)d_in[4];
    Ptrs11 prm;
    for (int i = 0; i < 11; i++) prm.p[i] = (const float*)d_in[5 + i];
    int V = in_sizes[0] / 3;
    float* out = (float*)d_out;

    lbs_pose_kernel<<<1, 384>>>(joints, disp, rdis, prm, out, V);
    int nb = (V + VPB - 1) / VPB;
    lbs_vert_kernel<<<nb, TPB>>>(verts, weights, out, V);
}

// round 5
// speedup vs baseline: 1.2787x; 1.1673x over previous
#include <cuda_runtime.h>
#include <math.h>

#define NJ 23
#define NP 16
#define TPB 128   // threads per block
#define VPB 256   // vertices per block (2 per thread)

__constant__ int c_par[NJ]  = {-1,0,1,1,3,4,5,4,7,4,9,1,11,12,13,12,15,12,17,0,19,0,21};
__constant__ int c_slot[NJ] = {0,-1,-1,1,2,3,-1,4,-1,5,-1,6,7,8,-1,9,-1,10,-1,-1,-1,-1,-1};
__constant__ float c_scale[11] = {
    0.7853981633974483f, 1.5707963267948966f, 1.5707963267948966f,
    0.7853981633974483f, 0.7853981633974483f, 0.7853981633974483f,
    1.5707963267948966f, 1.5707963267948966f, 0.7853981633974483f,
    0.7853981633974483f, 0.7853981633974483f};
__constant__ int c_lvl[NJ]  = {0,1,2,2,3,4,5,4,5,4,5,2,3,4,5,4,5,4,5,1,2,1,2};

struct Ptrs11 { const float* p[11]; };

// f32x2 packed-FMA helpers (ptxas never emits these from C++)
__device__ __forceinline__ void fma2(unsigned long long& d, unsigned long long a,
                                     unsigned long long b) {
    asm("fma.rn.f32x2 %0, %1, %2, %0;" : "+l"(d) : "l"(a), "l"(b));
}
__device__ __forceinline__ unsigned long long pack2(float lo, float hi) {
    unsigned long long r;
    asm("mov.b64 %0, {%1, %2};" : "=l"(r) : "f"(lo), "f"(hi));
    return r;
}
__device__ __forceinline__ void unpack2(unsigned long long v, float& lo, float& hi) {
    asm("mov.b64 {%0, %1}, %2;" : "=f"(lo), "=f"(hi) : "l"(v));
}

// ---------------------------------------------------------------------------
// Fused kernel. Phase 1 (replicated per block): pose kinematics -> packed A
// matrices in smem (sA). Scratch for the kinematic chain (sG) aliases the
// weights slab (sU) which is loaded afterwards. Phase 2: 2 vertices/thread,
// pose-pairs processed in 2 passes of 4 to keep regs <= 128 (4 CTAs/SM).
// ---------------------------------------------------------------------------
__global__ void __launch_bounds__(TPB, 4)
lbs_fused_kernel(const float* __restrict__ verts,
                 const float* __restrict__ joints,
                 const float* __restrict__ weights,
                 const float* __restrict__ disp,
                 const float* __restrict__ rdis,
                 Ptrs11 prm,
                 float* __restrict__ out, int V)
{
    __shared__ __align__(16) float sA[NJ * 8 * 24];   // 17664 B, packed A pairs
    __shared__ __align__(16) float sU[VPB * NJ];      // 23552 B: sG scratch, then sW
    int t = threadIdx.x;

    // ================= Phase 1: pose (replicated in every block) ============
    // Each thread owns up to 3 (pose, joint) pairs: t, t+128, t+256 (<368).
    float Tl[3][12];
    #pragma unroll
    for (int k = 0; k < 3; k++) {
        int idx = t + k * TPB;
        if (idx < NP * NJ) {
            int p = idx / NJ, jj = idx - p * NJ;
            int s = c_slot[jj];
            float rx = 0.f, ry = 0.f, rz = 0.f;
            if (s >= 0) {
                const float* q = prm.p[s] + p * 3;
                float sc = c_scale[s];
                rx = sc * tanhf(q[0]); ry = sc * tanhf(q[1]); rz = sc * tanhf(q[2]);
            }
            float th = sqrtf(rx * rx + ry * ry + rz * rz + 1e-16f);
            float inv = 1.f / th;
            float ax = rx * inv, ay = ry * inv, az = rz * inv;
            float sn = sinf(th), cs = cosf(th), oc = 1.f - cs;
            float* T = Tl[k];
            T[0] = cs + oc * ax * ax;      T[1] = oc * ax * ay - sn * az; T[2]  = oc * ax * az + sn * ay;
            T[4] = oc * ax * ay + sn * az; T[5] = cs + oc * ay * ay;      T[6]  = oc * ay * az - sn * ax;
            T[8] = oc * ax * az - sn * ay; T[9] = oc * ay * az + sn * ax; T[10] = cs + oc * az * az;
            float relx = joints[jj * 3 + 0], rely = joints[jj * 3 + 1], relz = joints[jj * 3 + 2];
            if (jj > 0) {
                int pa = c_par[jj];
                relx -= joints[pa * 3 + 0];
                rely -= joints[pa * 3 + 1];
                relz -= joints[pa * 3 + 2];
            }
            T[3] = relx; T[7] = rely; T[11] = relz;
            if (jj == 0) {
                float* G = &sU[(p * NJ) * 12];
                #pragma unroll
                for (int i = 0; i < 12; i++) G[i] = T[i];
            }
        }
    }
    __syncthreads();

    // Kinematic chain level-by-level (depth 5). G in sU, own T in regs.
    #pragma unroll
    for (int l = 1; l <= 5; l++) {
        #pragma unroll
        for (int k = 0; k < 3; k++) {
            int idx = t + k * TPB;
            if (idx < NP * NJ) {
                int p = idx / NJ, jj = idx - p * NJ;
                if (c_lvl[jj] == l) {
                    const float* Gp = &sU[(p * NJ + c_par[jj]) * 12];
                    const float* T = Tl[k];
                    float* Gc = &sU[(p * NJ + jj) * 12];
                    #pragma unroll
                    for (int i = 0; i < 3; i++) {
                        float a0 = Gp[i * 4 + 0], a1 = Gp[i * 4 + 1], a2 = Gp[i * 4 + 2];
                        Gc[i * 4 + 0] = a0 * T[0] + a1 * T[4] + a2 * T[8];
                        Gc[i * 4 + 1] = a0 * T[1] + a1 * T[5] + a2 * T[9];
                        Gc[i * 4 + 2] = a0 * T[2] + a1 * T[6] + a2 * T[10];
                        Gc[i * 4 + 3] = a0 * T[3] + a1 * T[7] + a2 * T[11] + Gp[i * 4 + 3];
                    }
                }
            }
        }
        __syncthreads();
    }

    // Pack A = [G_R | G_t - G_R@j + shift] into sA; block 0 writes joint tail.
    #pragma unroll
    for (int k = 0; k < 3; k++) {
        int idx = t + k * TPB;
        if (idx < NP * NJ) {
            int p = idx / NJ, jj = idx - p * NJ;
            float sh0 = rdis[p * 3 + 0] + 3.f * tanhf(disp[p * 3 + 0]);
            float sh1 = rdis[p * 3 + 1] + 3.f * tanhf(disp[p * 3 + 1]);
            float sh2 = rdis[p * 3 + 2] + 3.f * tanhf(disp[p * 3 + 2]);
            const float* G = &sU[(p * NJ + jj) * 12];
            if (blockIdx.x == 0) {
                size_t jbase = (size_t)NP * V * 3 + ((size_t)p * NJ + jj) * 3;
                out[jbase + 0] = G[3]  + sh0;
                out[jbase + 1] = G[7]  + sh1;
                out[jbase + 2] = G[11] + sh2;
            }
            float jx = joints[jj * 3 + 0], jy = joints[jj * 3 + 1], jz = joints[jj * 3 + 2];
            int pp = p >> 1, par = p & 1;
            float* dst = sA + ((jj * 8 + pp) * 12) * 2 + par;
            float sh[3] = {sh0, sh1, sh2};
            #pragma unroll
            for (int i = 0; i < 3; i++) {
                float tr = G[i * 4 + 3] - (G[i * 4 + 0] * jx + G[i * 4 + 1] * jy + G[i * 4 + 2] * jz) + sh[i];
                dst[(i * 4 + 0) * 2] = G[i * 4 + 0];
                dst[(i * 4 + 1) * 2] = G[i * 4 + 1];
                dst[(i * 4 + 2) * 2] = G[i * 4 + 2];
                dst[(i * 4 + 3) * 2] = tr;
            }
        }
    }
    __syncthreads();   // sU (sG) reads done; safe to overwrite with weights

    // ================= Phase 2: skinning ====================================
    int base = blockIdx.x * VPB;
    {
        int rem = V - base;
        int nval = (rem >= VPB ? VPB : rem) * NJ;
        const float* slab = weights + (size_t)base * NJ;
        if (nval == VPB * NJ) {
            const float4* g4 = (const float4*)slab;
            float4* s4 = (float4*)sU;
            #pragma unroll 1
            for (int i = t; i < VPB * NJ / 4; i += TPB) s4[i] = g4[i];
        } else {
            #pragma unroll 1
            for (int i = t; i < nval; i += TPB) sU[i] = slab[i];
        }
    }
    __syncthreads();

    int v0 = base + t;
    int v1 = v0 + TPB;
    int vc0 = v0 < V ? v0 : V - 1;
    int vc1 = v1 < V ? v1 : V - 1;
    float x0 = verts[3 * vc0 + 0], y0 = verts[3 * vc0 + 1], z0 = verts[3 * vc0 + 2];
    float x1 = verts[3 * vc1 + 0], y1 = verts[3 * vc1 + 1], z1 = verts[3 * vc1 + 2];

    size_t slab = (size_t)V * 3;

    // Two passes over pose pairs (4 each) -> 48 accumulator regs per pass.
    #pragma unroll 1
    for (int half = 0; half < 2; half++) {
        unsigned long long acc0[4][3], acc1[4][3];
        #pragma unroll
        for (int pp = 0; pp < 4; pp++)
            #pragma unroll
            for (int i = 0; i < 3; i++) { acc0[pp][i] = 0ull; acc1[pp][i] = 0ull; }

        #pragma unroll 1
        for (int j = 0; j < NJ; j++) {
            float w0 = sU[t * NJ + j];
            float w1 = sU[(t + TPB) * NJ + j];
            unsigned long long a0 = pack2(w0 * x0, w0 * x0);
            unsigned long long a1 = pack2(w0 * y0, w0 * y0);
            unsigned long long a2 = pack2(w0 * z0, w0 * z0);
            unsigned long long a3 = pack2(w0, w0);
            unsigned long long b0 = pack2(w1 * x1, w1 * x1);
            unsigned long long b1 = pack2(w1 * y1, w1 * y1);
            unsigned long long b2 = pack2(w1 * z1, w1 * z1);
            unsigned long long b3 = pack2(w1, w1);
            const ulonglong2* r = (const ulonglong2*)(sA + j * 8 * 24) + half * 24;
            #pragma unroll
            for (int pp = 0; pp < 4; pp++) {
                ulonglong2 q0 = r[pp * 6 + 0], q1 = r[pp * 6 + 1], q2 = r[pp * 6 + 2];
                ulonglong2 q3 = r[pp * 6 + 3], q4 = r[pp * 6 + 4], q5 = r[pp * 6 + 5];
                fma2(acc0[pp][0], q0.x, a0); fma2(acc0[pp][0], q0.y, a1);
                fma2(acc0[pp][0], q1.x, a2); fma2(acc0[pp][0], q1.y, a3);
                fma2(acc0[pp][1], q2.x, a0); fma2(acc0[pp][1], q2.y, a1);
                fma2(acc0[pp][1], q3.x, a2); fma2(acc0[pp][1], q3.y, a3);
                fma2(acc0[pp][2], q4.x, a0); fma2(acc0[pp][2], q4.y, a1);
                fma2(acc0[pp][2], q5.x, a2); fma2(acc0[pp][2], q5.y, a3);
                fma2(acc1[pp][0], q0.x, b0); fma2(acc1[pp][0], q0.y, b1);
                fma2(acc1[pp][0], q1.x, b2); fma2(acc1[pp][0], q1.y, b3);
                fma2(acc1[pp][1], q2.x, b0); fma2(acc1[pp][1], q2.y, b1);
                fma2(acc1[pp][1], q3.x, b2); fma2(acc1[pp][1], q3.y, b3);
                fma2(acc1[pp][2], q4.x, b0); fma2(acc1[pp][2], q4.y, b1);
                fma2(acc1[pp][2], q5.x, b2); fma2(acc1[pp][2], q5.y, b3);
            }
        }

        if (v0 < V) {
            size_t vb = (size_t)v0 * 3;
            #pragma unroll
            for (int pp = 0; pp < 4; pp++) {
                int ppg = half * 4 + pp;
                size_t c0 = (size_t)(2 * ppg) * slab + vb;
                size_t c1 = c0 + slab;
                #pragma unroll
                for (int i = 0; i < 3; i++) {
                    float lo, hi;
                    unpack2(acc0[pp][i], lo, hi);
                    out[c0 + i] = lo;
                    out[c1 + i] = hi;
                }
            }
        }
        if (v1 < V) {
            size_t vb = (size_t)v1 * 3;
            #pragma unroll
            for (int pp = 0; pp < 4; pp++) {
                int ppg = half * 4 + pp;
                size_t c0 = (size_t)(2 * ppg) * slab + vb;
                size_t c1 = c0 + slab;
                #pragma unroll
                for (int i = 0; i < 3; i++) {
                    float lo, hi;
                    unpack2(acc1[pp][i], lo, hi);
                    out[c0 + i] = lo;
                    out[c1 + i] = hi;
                }
            }
        }
    }
}

// ---------------------------------------------------------------------------
// Launch: single fused kernel.
// ---------------------------------------------------------------------------
extern "C" void kernel_launch(void* const* d_in, const int* in_sizes, int n_in,
                              void* d_out, int out_size)
{
    const float* verts   = (const float*)d_in[0];
    const float* joints  = (const float*)d_in[1];
    const float* weights = (const float*)d_in[2];
    const float* disp    = (const float*)d_in[3];
    const float* rdis    = (const float*)d_in[4];
    Ptrs11 prm;
    for (int i = 0; i < 11; i++) prm.p[i] = (const float*)d_in[5 + i];
    int V = in_sizes[0] / 3;
    float* out = (float*)d_out;

    int nb = (V + VPB - 1) / VPB;
    lbs_fused_kernel<<<nb, TPB>>>(verts, joints, weights, disp, rdis, prm, out, V);
}